// round 15
// baseline (speedup 1.0000x reference)
#include <cuda_runtime.h>
#include <cstdint>
#include <cstring>

#define BATCH 32
#define TT    512
#define NGATE 1024   // 4*H
#define HDIM  256
#define OUTW  512

// Scratch (static device globals — no allocation allowed)
__device__ float g_xg[(size_t)2 * BATCH * TT * NGATE];   // pre-activations (both dirs)
__device__ float g_h1[(size_t)BATCH * TT * OUTW];        // layer-0 output (fwd||bwd concat)

// ---------------- f32x2 helpers (recurrence) ----------------
__device__ __forceinline__ void ffma2(unsigned long long& d, unsigned long long a, unsigned long long b) {
    asm("fma.rn.f32x2 %0, %1, %2, %0;" : "+l"(d) : "l"(a), "l"(b));
}
__device__ __forceinline__ float fold2(unsigned long long v) {
    float2 f; memcpy(&f, &v, 8); return f.x + f.y;
}
__device__ __forceinline__ unsigned long long pack2(float lo, float hi) {
    unsigned long long u;
    asm("mov.b64 %0, {%1, %2};" : "=l"(u) : "f"(lo), "f"(hi));
    return u;
}

// ===========================================================================
// 3xTF32 mma.sync GEMM (unchanged from R14 — best passing)
// ===========================================================================
__device__ __forceinline__ uint32_t to_tf32(float x) {
    uint32_t r;
    asm("cvt.rna.tf32.f32 %0, %1;" : "=r"(r) : "f"(x));
    return r;
}
__device__ __forceinline__ void mma_tf32(float c[4],
    uint32_t a0, uint32_t a1, uint32_t a2, uint32_t a3,
    uint32_t b0, uint32_t b1)
{
    asm("mma.sync.aligned.m16n8k8.row.col.f32.tf32.tf32.f32 "
        "{%0,%1,%2,%3}, {%4,%5,%6,%7}, {%8,%9}, {%0,%1,%2,%3};"
        : "+f"(c[0]), "+f"(c[1]), "+f"(c[2]), "+f"(c[3])
        : "r"(a0), "r"(a1), "r"(a2), "r"(a3), "r"(b0), "r"(b1));
}

#define SA_AH 0
#define SA_AL 5160
#define SA_BH 10320
#define SA_BL 12920
#define SA_TOTAL 15520   // uint32 words -> 62080 bytes dynamic smem

__global__ __launch_bounds__(256, 1) void gemm_tc32(
    const float* __restrict__ src, int K, int nst,
    const float* __restrict__ Wf, const float* __restrict__ bf,
    const float* __restrict__ Wb, const float* __restrict__ bb)
{
    extern __shared__ __align__(16) uint32_t sm[];
    const int dir = blockIdx.z;
    const float* __restrict__ W    = dir ? Wb : Wf;
    const float* __restrict__ bias = dir ? bb : bf;
    const int j0 = blockIdx.x * 64;
    const int r0 = blockIdx.y * 128;

    const int tid  = threadIdx.x;
    const int wid  = tid >> 5;
    const int lane = tid & 31;
    const int g    = lane >> 2;
    const int tg   = lane & 3;
    const int mrow = (wid & 3) * 32;
    const int ncol = (wid >> 2) * 32;

    const int arow  = tid >> 1;
    const int ahalf = tid & 1;
    const int brow  = tid >> 2;
    const int bq4   = (tid & 3) * 4;
    const float* aptr = src + (size_t)(r0 + arow) * K + ahalf * 8;
    const float* bptr = W   + (size_t)(j0 + brow) * K + bq4;

    float c[2][4][4];
    #pragma unroll
    for (int i = 0; i < 2; i++)
        #pragma unroll
        for (int jn = 0; jn < 4; jn++)
            #pragma unroll
            for (int u = 0; u < 4; u++) c[i][jn][u] = 0.f;

    float apf[8]; float bpf[4];
    auto ldg_stage = [&](int s) {
        float4 v0 = *(const float4*)(aptr + s * 16);
        float4 v1 = *(const float4*)(aptr + s * 16 + 4);
        apf[0]=v0.x; apf[1]=v0.y; apf[2]=v0.z; apf[3]=v0.w;
        apf[4]=v1.x; apf[5]=v1.y; apf[6]=v1.z; apf[7]=v1.w;
        float4 w0 = *(const float4*)(bptr + s * 16);
        bpf[0]=w0.x; bpf[1]=w0.y; bpf[2]=w0.z; bpf[3]=w0.w;
    };
    auto sts_stage = [&](int buf) {
        uint32_t* ah = sm + SA_AH + buf * 2580 + ahalf * 1290 + arow * 10;
        uint32_t* al = sm + SA_AL + buf * 2580 + ahalf * 1290 + arow * 10;
        #pragma unroll
        for (int q = 0; q < 4; q++) {
            uint32_t h0 = to_tf32(apf[q]);
            uint32_t h1 = to_tf32(apf[q + 4]);
            uint32_t l0 = to_tf32(apf[q] - __uint_as_float(h0));
            uint32_t l1 = to_tf32(apf[q + 4] - __uint_as_float(h1));
            *(uint2*)(ah + q * 2) = make_uint2(h0, h1);
            *(uint2*)(al + q * 2) = make_uint2(l0, l1);
        }
        uint32_t* bh = sm + SA_BH + buf * 1300;
        uint32_t* bl = sm + SA_BL + buf * 1300;
        #pragma unroll
        for (int qq = 0; qq < 4; qq++) {
            int k  = bq4 + qq;
            int kb = k >> 3;
            int kk = k & 7;
            int wd = kb * 650 + brow * 10 + (kk & 3) * 2 + (kk >> 2);
            uint32_t hi = to_tf32(bpf[qq]);
            uint32_t lo = to_tf32(bpf[qq] - __uint_as_float(hi));
            bh[wd] = hi;
            bl[wd] = lo;
        }
    };
    auto compute_stage = [&](int buf) {
        const uint32_t* ah = sm + SA_AH + buf * 2580;
        const uint32_t* al = sm + SA_AL + buf * 2580;
        const uint32_t* bh = sm + SA_BH + buf * 1300;
        const uint32_t* bl = sm + SA_BL + buf * 1300;
        #pragma unroll
        for (int kb = 0; kb < 2; kb++) {
            uint32_t fah[2][4], fal[2][4], fbh[4][2], fbl[4][2];
            #pragma unroll
            for (int i = 0; i < 2; i++) {
                const int base = kb * 1290 + (mrow + i * 16 + g) * 10 + tg * 2;
                uint2 h0 = *(const uint2*)(ah + base);
                uint2 h1 = *(const uint2*)(ah + base + 80);   // row+8
                uint2 l0 = *(const uint2*)(al + base);
                uint2 l1 = *(const uint2*)(al + base + 80);
                fah[i][0] = h0.x; fah[i][2] = h0.y;
                fah[i][1] = h1.x; fah[i][3] = h1.y;
                fal[i][0] = l0.x; fal[i][2] = l0.y;
                fal[i][1] = l1.x; fal[i][3] = l1.y;
            }
            #pragma unroll
            for (int jn = 0; jn < 4; jn++) {
                const int wb = kb * 650 + (ncol + jn * 8 + g) * 10 + tg * 2;
                uint2 hb = *(const uint2*)(bh + wb);
                uint2 lb = *(const uint2*)(bl + wb);
                fbh[jn][0] = hb.x; fbh[jn][1] = hb.y;
                fbl[jn][0] = lb.x; fbl[jn][1] = lb.y;
            }
            #pragma unroll
            for (int i = 0; i < 2; i++)
                #pragma unroll
                for (int jn = 0; jn < 4; jn++) {
                    mma_tf32(c[i][jn], fah[i][0], fah[i][1], fah[i][2], fah[i][3], fbh[jn][0], fbh[jn][1]);
                    mma_tf32(c[i][jn], fah[i][0], fah[i][1], fah[i][2], fah[i][3], fbl[jn][0], fbl[jn][1]);
                    mma_tf32(c[i][jn], fal[i][0], fal[i][1], fal[i][2], fal[i][3], fbh[jn][0], fbh[jn][1]);
                }
        }
    };

    ldg_stage(0);
    sts_stage(0);
    __syncthreads();
    for (int s = 0; s < nst; ++s) {
        if (s + 1 < nst) ldg_stage(s + 1);
        compute_stage(s & 1);
        if (s + 1 < nst) sts_stage((s + 1) & 1);
        __syncthreads();
    }

    float* outp = g_xg + ((size_t)dir * (BATCH * TT)) * NGATE;
    #pragma unroll
    for (int i = 0; i < 2; i++) {
        #pragma unroll
        for (int jn = 0; jn < 4; jn++) {
            const int col = j0 + ncol + jn * 8 + 2 * tg;
            const float b0v = __ldg(&bias[col]);
            const float b1v = __ldg(&bias[col + 1]);
            const int row = r0 + mrow + i * 16 + g;
            float2 v0 = make_float2(c[i][jn][0] + b0v, c[i][jn][1] + b1v);
            float2 v1 = make_float2(c[i][jn][2] + b0v, c[i][jn][3] + b1v);
            *(float2*)&outp[(size_t)row * NGATE + col] = v0;
            *(float2*)&outp[(size_t)(row + 8) * NGATE + col] = v1;
        }
    }
}

// ---------------------------------------------------------------------------
// Recurrence v9: per-source mbarriers. full_mbar[buf][src] (16 total, count=1,
// expect 512B each = 32 messages from one source CTA). Warp w waits mbar[b][w]
// in parallel; __syncthreads publishes. 8x less completion serialization per
// mbar word vs the single-mbar R7 design.
// ---------------------------------------------------------------------------
__device__ __forceinline__ float sigmoid_fast(float x) {
    return __fdividef(1.f, 1.f + __expf(-x));
}
__device__ __forceinline__ float tanh_fast(float x) {
    float xc = fminf(fmaxf(x, -15.f), 15.f);
    float e = __expf(2.f * xc);
    return __fdividef(e - 1.f, e + 1.f);
}

__device__ __forceinline__ void mbar_wait_cl(uint32_t mb, uint32_t par) {
    uint32_t done;
    asm volatile(
        "{\n\t.reg .pred p;\n\t"
        "mbarrier.try_wait.parity.acquire.cluster.shared::cta.b64 p, [%1], %2, 0x989680;\n\t"
        "selp.b32 %0, 1, 0, p;\n\t}"
        : "=r"(done) : "r"(mb), "r"(par) : "memory");
    while (!done) {
        asm volatile(
            "{\n\t.reg .pred p;\n\t"
            "mbarrier.try_wait.parity.acquire.cluster.shared::cta.b64 p, [%1], %2, 0x989680;\n\t"
            "selp.b32 %0, 1, 0, p;\n\t}"
            : "=r"(done) : "r"(mb), "r"(par) : "memory");
    }
}

__global__ __launch_bounds__(256, 1) __cluster_dims__(8, 1, 1)
void lstm_rec(const float* __restrict__ whhF, const float* __restrict__ whhB,
              float* __restrict__ out)
{
    __shared__ __align__(16) float h_s[2 * 1024];   // [2 buf][4 batch][256]
    __shared__ float g_s [512];
    __shared__ float rsum[512];
    __shared__ __align__(16) float hstage[128];
    __shared__ __align__(8) unsigned long long full_mbar[16];   // [buf][src]

    const int tid   = threadIdx.x;
    const int j     = tid & 127;
    const int kh    = tid >> 7;
    const int wid   = tid >> 5;          // warp 0..7
    const int lane  = tid & 31;
    const int brank = blockIdx.x & 7;
    const int cid   = blockIdx.x >> 3;
    const int dir   = cid >> 3;
    const int bg    = cid & 7;
    const float* __restrict__ whh = dir ? whhB : whhF;

    const int gate = j >> 5;
    const int kl   = j & 31;
    const int grow = (gate << 8) + (brank << 5) + kl;

    unsigned long long Wreg[64];
    {
        const float* wrow = whh + (size_t)grow * HDIM + (kh << 7);
        #pragma unroll
        for (int q = 0; q < 64; ++q) {
            float2 w = *(const float2*)(wrow + 2 * q);
            memcpy(&Wreg[q], &w, 8);
        }
    }

    uint32_t h_local, m_local;
    asm volatile("{ .reg .u64 t; cvta.to.shared.u64 t, %1; cvt.u32.u64 %0, t; }"
                 : "=r"(h_local) : "l"((const float*)h_s));
    asm volatile("{ .reg .u64 t; cvta.to.shared.u64 t, %1; cvt.u32.u64 %0, t; }"
                 : "=r"(m_local) : "l"((const unsigned long long*)full_mbar));

    // init 16 mbars: count=1, expect 512 B each (32 messages from one source)
    if (tid == 0) {
        #pragma unroll
        for (int i = 0; i < 16; i++)
            asm volatile("mbarrier.init.shared.b64 [%0], %1;"
                         :: "r"(m_local + i * 8), "r"(1u) : "memory");
    }
    if (tid < 128) hstage[tid] = 0.f;
    __syncthreads();
    if (tid == 0) {
        #pragma unroll
        for (int i = 0; i < 16; i++)
            asm volatile("mbarrier.arrive.expect_tx.shared.b64 _, [%0], %1;"
                         :: "r"(m_local + i * 8), "r"(512u) : "memory");
    }
    __syncthreads();
    asm volatile("barrier.cluster.arrive.aligned;\n\tbarrier.cluster.wait.aligned;" ::: "memory");

    // push mapping: this thread pushes one float4 to peer (tid>>5)
    uint32_t peer_h, peer_m;
    {
        uint32_t rk = (uint32_t)(tid >> 5);
        asm volatile("mapa.shared::cluster.u32 %0, %1, %2;" : "=r"(peer_h) : "r"(h_local), "r"(rk));
        asm volatile("mapa.shared::cluster.u32 %0, %1, %2;" : "=r"(peer_m) : "r"(m_local), "r"(rk));
    }
    const int i5 = tid & 31;
    const uint32_t push_off = ((uint32_t)(i5 >> 3) << 10) + ((uint32_t)brank << 7) + ((uint32_t)(i5 & 7) << 4);
    const uint32_t my_src_off = (uint32_t)brank * 8u;   // mbar slot offset for our source id

    // seed buffer 0 with zeros (completes mbar[0][brank] at each peer)
    {
        const float4 v = *(const float4*)&hstage[i5 << 2];   // zeros
        asm volatile("st.async.shared::cluster.mbarrier::complete_tx::bytes.v4.f32 "
                     "[%0], {%1, %2, %3, %4}, [%5];"
                     :: "r"(peer_h + push_off), "f"(v.x), "f"(v.y), "f"(v.z), "f"(v.w),
                        "r"(peer_m + my_src_off) : "memory");
    }

    const float* xgb = g_xg + (((size_t)dir * BATCH + bg * 4) * TT) * NGATE;

    float c_state = 0.f;
    int t = dir ? (TT - 1) : 0;
    const int tstep = dir ? -1 : 1;

    float x0 = 0.f, x1 = 0.f, x2 = 0.f, x3 = 0.f;
    if (kh == 0) {
        x0 = xgb[((size_t)0 * TT + t) * NGATE + grow];
        x1 = xgb[((size_t)1 * TT + t) * NGATE + grow];
        x2 = xgb[((size_t)2 * TT + t) * NGATE + grow];
        x3 = xgb[((size_t)3 * TT + t) * NGATE + grow];
    }

    int ph0 = 0, ph1 = 0;
    for (int it = 0; it < TT; ++it) {
        const int b = it & 1;
        // ---- parallel wait: warp w waits mbar[b][w]; syncthreads publishes ----
        {
            const uint32_t mb = m_local + (uint32_t)(b * 8 + wid) * 8u;
            mbar_wait_cl(mb, (uint32_t)(b ? ph1 : ph0));
            if (lane == 0 && it < TT - 1) {
                asm volatile("mbarrier.arrive.expect_tx.shared.b64 _, [%0], %1;"
                             :: "r"(mb), "r"(512u) : "memory");
            }
        }
        if (b) ph1 ^= 1; else ph0 ^= 1;
        __syncthreads();

        unsigned long long acc0, acc1, acc2, acc3;
        if (kh == 0) {
            acc0 = pack2(x0, 0.f); acc1 = pack2(x1, 0.f);
            acc2 = pack2(x2, 0.f); acc3 = pack2(x3, 0.f);
        } else {
            acc0 = acc1 = acc2 = acc3 = 0ull;
        }

        const ulonglong2* hptr = reinterpret_cast<const ulonglong2*>(h_s + (b << 10) + (kh << 7));
        #pragma unroll
        for (int q = 0; q < 32; ++q) {
            ulonglong2 ha = hptr[q];
            ulonglong2 hb = hptr[q + 64];
            ulonglong2 hc = hptr[q + 128];
            ulonglong2 hd = hptr[q + 192];
            unsigned long long w0 = Wreg[2 * q], w1 = Wreg[2 * q + 1];
            ffma2(acc0, w0, ha.x); ffma2(acc1, w0, hb.x);
            ffma2(acc2, w0, hc.x); ffma2(acc3, w0, hd.x);
            ffma2(acc0, w1, ha.y); ffma2(acc1, w1, hb.y);
            ffma2(acc2, w1, hc.y); ffma2(acc3, w1, hd.y);
        }

        float s0 = fold2(acc0), s1 = fold2(acc1), s2 = fold2(acc2), s3 = fold2(acc3);
        if (kh == 0) {
            g_s[      j] = s0; g_s[128 + j] = s1; g_s[256 + j] = s2; g_s[384 + j] = s3;
        } else {
            rsum[      j] = s0; rsum[128 + j] = s1; rsum[256 + j] = s2; rsum[384 + j] = s3;
        }
        __syncthreads();

        float hval = 0.f;
        if (tid < 128) {
            const int bb   = tid >> 5;
            const int kloc = tid & 31;
            const int base = bb * 128 + kloc;
            float gi = g_s[base     ] + rsum[base     ];
            float gf = g_s[base + 32] + rsum[base + 32];
            float gg = g_s[base + 64] + rsum[base + 64];
            float go = g_s[base + 96] + rsum[base + 96];
            float i_ = sigmoid_fast(gi);
            float f_ = sigmoid_fast(gf);
            float g_ = tanh_fast(gg);
            float o_ = sigmoid_fast(go);
            c_state = f_ * c_state + i_ * g_;
            hval = o_ * tanh_fast(c_state);
            hstage[tid] = hval;
        }
        __syncthreads();

        // ---- push h(it) into peers' buffer b^1; complete on mbar[(b^1)][brank] ----
        {
            const float4 v = *(const float4*)&hstage[i5 << 2];
            const uint32_t dst = peer_h + ((uint32_t)(b ^ 1) << 12) + push_off;
            asm volatile("st.async.shared::cluster.mbarrier::complete_tx::bytes.v4.f32 "
                         "[%0], {%1, %2, %3, %4}, [%5];"
                         :: "r"(dst), "f"(v.x), "f"(v.y), "f"(v.z), "f"(v.w),
                            "r"(peer_m + ((uint32_t)(b ^ 1) * 8u + (uint32_t)brank) * 8u) : "memory");
        }

        if (tid < 128) {
            const int bb   = tid >> 5;
            const int kloc = tid & 31;
            out[(((size_t)(bg * 4 + bb)) * TT + t) * OUTW + (dir << 8) + (brank << 5) + kloc] = hval;
        }
        if (kh == 0 && it + 1 < TT) {
            const int tnx = t + tstep;
            x0 = xgb[((size_t)0 * TT + tnx) * NGATE + grow];
            x1 = xgb[((size_t)1 * TT + tnx) * NGATE + grow];
            x2 = xgb[((size_t)2 * TT + tnx) * NGATE + grow];
            x3 = xgb[((size_t)3 * TT + tnx) * NGATE + grow];
        }

        t += tstep;
    }

    // drain: final pushes (it=TT-1, b=1) completed buf-0 mbars; consume them
    {
        const uint32_t mb = m_local + (uint32_t)(0 * 8 + wid) * 8u;
        mbar_wait_cl(mb, (uint32_t)ph0);
    }
    asm volatile("barrier.cluster.arrive.aligned;\n\tbarrier.cluster.wait.aligned;" ::: "memory");
}

// ---------------------------------------------------------------------------
extern "C" void kernel_launch(void* const* d_in, const int* in_sizes, int n_in,
                              void* d_out, int out_size)
{
    const float* x         = (const float*)d_in[0];
    const float* w_ih_l0f  = (const float*)d_in[1];
    const float* w_hh_l0f  = (const float*)d_in[2];
    const float* b_l0f     = (const float*)d_in[3];
    const float* w_ih_l0b  = (const float*)d_in[4];
    const float* w_hh_l0b  = (const float*)d_in[5];
    const float* b_l0b     = (const float*)d_in[6];
    const float* w_ih_l1f  = (const float*)d_in[7];
    const float* w_hh_l1f  = (const float*)d_in[8];
    const float* b_l1f     = (const float*)d_in[9];
    const float* w_ih_l1b  = (const float*)d_in[10];
    const float* w_hh_l1b  = (const float*)d_in[11];
    const float* b_l1b     = (const float*)d_in[12];
    float* out = (float*)d_out;

    float* h1 = nullptr;
    cudaGetSymbolAddress((void**)&h1, g_h1);

    const int smemB = SA_TOTAL * 4;   // 62080 B
    cudaFuncSetAttribute(gemm_tc32, cudaFuncAttributeMaxDynamicSharedMemorySize, smemB);

    dim3 tgrid(16, 128, 2);   // N/64, M/128, dirs

    // Layer 0 (K=256, 16 stages of 16)
    gemm_tc32<<<tgrid, 256, smemB>>>(x, 256, 16, w_ih_l0f, b_l0f, w_ih_l0b, b_l0b);
    lstm_rec<<<128, 256>>>(w_hh_l0f, w_hh_l0b, h1);

    // Layer 1 (K=512, 32 stages of 16)
    gemm_tc32<<<tgrid, 256, smemB>>>(h1, 512, 32, w_ih_l1f, b_l1f, w_ih_l1b, b_l1b);
    lstm_rec<<<128, 256>>>(w_hh_l1f, w_hh_l1b, out);
}

// round 16
// speedup vs baseline: 1.1346x; 1.1346x over previous
#include <cuda_runtime.h>
#include <cuda_bf16.h>
#include <cstdint>
#include <cstring>

#define BATCH 32
#define TT    512
#define NGATE 1024   // 4*H
#define HDIM  256
#define OUTW  512

// Scratch (static device globals — no allocation allowed)
__device__ float g_xg[(size_t)2 * BATCH * TT * NGATE];   // pre-activations (both dirs)
__device__ float g_h1[(size_t)BATCH * TT * OUTW];        // layer-0 output (fwd||bwd concat)

// ---------------- f32x2 helpers (recurrence) ----------------
__device__ __forceinline__ void ffma2(unsigned long long& d, unsigned long long a, unsigned long long b) {
    asm("fma.rn.f32x2 %0, %1, %2, %0;" : "+l"(d) : "l"(a), "l"(b));
}
__device__ __forceinline__ float fold2(unsigned long long v) {
    float2 f; memcpy(&f, &v, 8); return f.x + f.y;
}
__device__ __forceinline__ unsigned long long pack2(float lo, float hi) {
    unsigned long long u;
    asm("mov.b64 %0, {%1, %2};" : "=l"(u) : "f"(lo), "f"(hi));
    return u;
}

// ===========================================================================
// bf16 2-split mma.sync GEMM:  D = xh*Wh + xh*Wl + xl*Wh   (bf16 m16n8k16)
// CTA tile M=128 x N=64, K-stage 16, 8 warps (4M x 2N), warp tile 32x32.
// smem words: X[buf][row*10 + (kp&3)*2 + (kp>>2)]; kp = k-pair 0..7.
// Fragments: A LDS.64 {a0,a2}/{a1,a3}; B LDS.64 {b0,b1}. 24 mma + 16 LDS.64
// per stage (vs 48 mma in the 3xTF32 version). 31KB smem -> 2 CTAs/SM.
// ===========================================================================
__device__ __forceinline__ uint32_t pack_bf16x2(float lo_elem, float hi_elem) {
    __nv_bfloat162 v;
    v.x = __float2bfloat16(lo_elem);
    v.y = __float2bfloat16(hi_elem);
    uint32_t u; memcpy(&u, &v, 4);
    return u;
}
__device__ __forceinline__ float bf_hi_part(float x) {
    return __bfloat162float(__float2bfloat16(x));
}
__device__ __forceinline__ void mma_bf16(float c[4],
    uint32_t a0, uint32_t a1, uint32_t a2, uint32_t a3,
    uint32_t b0, uint32_t b1)
{
    asm("mma.sync.aligned.m16n8k16.row.col.f32.bf16.bf16.f32 "
        "{%0,%1,%2,%3}, {%4,%5,%6,%7}, {%8,%9}, {%0,%1,%2,%3};"
        : "+f"(c[0]), "+f"(c[1]), "+f"(c[2]), "+f"(c[3])
        : "r"(a0), "r"(a1), "r"(a2), "r"(a3), "r"(b0), "r"(b1));
}

#define SB_AH 0       // 2 bufs x 1280 words (128 rows x 10)
#define SB_AL 2560
#define SB_BH 5120    // 2 bufs x 640 words (64 rows x 10)
#define SB_BL 6400
#define SB_TOTAL 7680 // words -> 30720 bytes dynamic smem

__global__ __launch_bounds__(256, 2) void gemm_bf(
    const float* __restrict__ src, int K, int nst,
    const float* __restrict__ Wf, const float* __restrict__ bf,
    const float* __restrict__ Wb, const float* __restrict__ bb)
{
    extern __shared__ __align__(16) uint32_t sm[];
    const int dir = blockIdx.z;
    const float* __restrict__ W    = dir ? Wb : Wf;
    const float* __restrict__ bias = dir ? bb : bf;
    const int j0 = blockIdx.x * 64;
    const int r0 = blockIdx.y * 128;

    const int tid  = threadIdx.x;
    const int wid  = tid >> 5;
    const int lane = tid & 31;
    const int g    = lane >> 2;
    const int tg   = lane & 3;
    const int mrow = (wid & 3) * 32;
    const int ncol = (wid >> 2) * 32;

    const int arow  = tid >> 1;
    const int ahalf = tid & 1;
    const int brow  = tid >> 2;
    const int bq4   = (tid & 3) * 4;
    const float* aptr = src + (size_t)(r0 + arow) * K + ahalf * 8;
    const float* bptr = W   + (size_t)(j0 + brow) * K + bq4;

    float c[2][4][4];
    #pragma unroll
    for (int i = 0; i < 2; i++)
        #pragma unroll
        for (int jn = 0; jn < 4; jn++)
            #pragma unroll
            for (int u = 0; u < 4; u++) c[i][jn][u] = 0.f;

    float apf[8]; float bpf[4];
    auto ldg_stage = [&](int s) {
        float4 v0 = *(const float4*)(aptr + s * 16);
        float4 v1 = *(const float4*)(aptr + s * 16 + 4);
        apf[0]=v0.x; apf[1]=v0.y; apf[2]=v0.z; apf[3]=v0.w;
        apf[4]=v1.x; apf[5]=v1.y; apf[6]=v1.z; apf[7]=v1.w;
        float4 w0 = *(const float4*)(bptr + s * 16);
        bpf[0]=w0.x; bpf[1]=w0.y; bpf[2]=w0.z; bpf[3]=w0.w;
    };
    auto sts_stage = [&](int buf) {
        // A: thread owns kpairs kp = ahalf*4 + qq, qq 0..3
        uint32_t* ah = sm + SB_AH + buf * 1280 + arow * 10;
        uint32_t* al = sm + SB_AL + buf * 1280 + arow * 10;
        #pragma unroll
        for (int qq = 0; qq < 4; qq++) {
            const int kp  = ahalf * 4 + qq;
            const int pos = (kp & 3) * 2 + (kp >> 2);
            float x0 = apf[2 * qq], x1 = apf[2 * qq + 1];
            float h0 = bf_hi_part(x0), h1 = bf_hi_part(x1);
            ah[pos] = pack_bf16x2(x0, x1);            // rn-rounded his
            al[pos] = pack_bf16x2(x0 - h0, x1 - h1);  // residuals
        }
        // B: thread owns kpairs kp = (tid&3)*2 + qq2, qq2 0..1
        uint32_t* bh = sm + SB_BH + buf * 640 + brow * 10;
        uint32_t* bl = sm + SB_BL + buf * 640 + brow * 10;
        #pragma unroll
        for (int qq2 = 0; qq2 < 2; qq2++) {
            const int kp  = (tid & 3) * 2 + qq2;
            const int pos = (kp & 3) * 2 + (kp >> 2);
            float x0 = bpf[2 * qq2], x1 = bpf[2 * qq2 + 1];
            float h0 = bf_hi_part(x0), h1 = bf_hi_part(x1);
            bh[pos] = pack_bf16x2(x0, x1);
            bl[pos] = pack_bf16x2(x0 - h0, x1 - h1);
        }
    };
    auto compute_stage = [&](int buf) {
        const uint32_t* ah = sm + SB_AH + buf * 1280;
        const uint32_t* al = sm + SB_AL + buf * 1280;
        const uint32_t* bh = sm + SB_BH + buf * 640;
        const uint32_t* bl = sm + SB_BL + buf * 640;
        uint32_t fah[2][4], fal[2][4], fbh[4][2], fbl[4][2];
        #pragma unroll
        for (int i = 0; i < 2; i++) {
            const int base = (mrow + i * 16 + g) * 10 + tg * 2;
            uint2 h0 = *(const uint2*)(ah + base);        // {a0, a2}
            uint2 h1 = *(const uint2*)(ah + base + 80);   // {a1, a3} (row+8)
            uint2 l0 = *(const uint2*)(al + base);
            uint2 l1 = *(const uint2*)(al + base + 80);
            fah[i][0] = h0.x; fah[i][2] = h0.y;
            fah[i][1] = h1.x; fah[i][3] = h1.y;
            fal[i][0] = l0.x; fal[i][2] = l0.y;
            fal[i][1] = l1.x; fal[i][3] = l1.y;
        }
        #pragma unroll
        for (int jn = 0; jn < 4; jn++) {
            const int wb = (ncol + jn * 8 + g) * 10 + tg * 2;
            uint2 hb = *(const uint2*)(bh + wb);
            uint2 lb = *(const uint2*)(bl + wb);
            fbh[jn][0] = hb.x; fbh[jn][1] = hb.y;
            fbl[jn][0] = lb.x; fbl[jn][1] = lb.y;
        }
        #pragma unroll
        for (int i = 0; i < 2; i++)
            #pragma unroll
            for (int jn = 0; jn < 4; jn++) {
                mma_bf16(c[i][jn], fah[i][0], fah[i][1], fah[i][2], fah[i][3], fbh[jn][0], fbh[jn][1]);
                mma_bf16(c[i][jn], fah[i][0], fah[i][1], fah[i][2], fah[i][3], fbl[jn][0], fbl[jn][1]);
                mma_bf16(c[i][jn], fal[i][0], fal[i][1], fal[i][2], fal[i][3], fbh[jn][0], fbh[jn][1]);
            }
    };

    ldg_stage(0);
    sts_stage(0);
    __syncthreads();
    for (int s = 0; s < nst; ++s) {
        if (s + 1 < nst) ldg_stage(s + 1);
        compute_stage(s & 1);
        if (s + 1 < nst) sts_stage((s + 1) & 1);
        __syncthreads();
    }

    float* outp = g_xg + ((size_t)dir * (BATCH * TT)) * NGATE;
    #pragma unroll
    for (int i = 0; i < 2; i++) {
        #pragma unroll
        for (int jn = 0; jn < 4; jn++) {
            const int col = j0 + ncol + jn * 8 + 2 * tg;
            const float b0v = __ldg(&bias[col]);
            const float b1v = __ldg(&bias[col + 1]);
            const int row = r0 + mrow + i * 16 + g;
            float2 v0 = make_float2(c[i][jn][0] + b0v, c[i][jn][1] + b1v);
            float2 v1 = make_float2(c[i][jn][2] + b0v, c[i][jn][3] + b1v);
            *(float2*)&outp[(size_t)row * NGATE + col] = v0;
            *(float2*)&outp[(size_t)(row + 8) * NGATE + col] = v1;
        }
    }
}

// ---------------------------------------------------------------------------
// Recurrence (EXACT R14 best): st.async + tx-count mbar, leader-warp wait.
// ---------------------------------------------------------------------------
__device__ __forceinline__ float sigmoid_fast(float x) {
    return __fdividef(1.f, 1.f + __expf(-x));
}
__device__ __forceinline__ float tanh_fast(float x) {
    float xc = fminf(fmaxf(x, -15.f), 15.f);
    float e = __expf(2.f * xc);
    return __fdividef(e - 1.f, e + 1.f);
}

__global__ __launch_bounds__(256, 1) __cluster_dims__(8, 1, 1)
void lstm_rec(const float* __restrict__ whhF, const float* __restrict__ whhB,
              float* __restrict__ out)
{
    __shared__ __align__(16) float h_s[2 * 1024];   // [2 buf][4 batch][256]
    __shared__ float g_s [512];
    __shared__ float rsum[512];
    __shared__ __align__(16) float hstage[128];
    __shared__ __align__(8) unsigned long long full_mbar[2];

    const int tid   = threadIdx.x;
    const int j     = tid & 127;
    const int kh    = tid >> 7;
    const int brank = blockIdx.x & 7;
    const int cid   = blockIdx.x >> 3;
    const int dir   = cid >> 3;
    const int bg    = cid & 7;
    const float* __restrict__ whh = dir ? whhB : whhF;

    const int gate = j >> 5;
    const int kl   = j & 31;
    const int grow = (gate << 8) + (brank << 5) + kl;

    unsigned long long Wreg[64];
    {
        const float* wrow = whh + (size_t)grow * HDIM + (kh << 7);
        #pragma unroll
        for (int q = 0; q < 64; ++q) {
            float2 w = *(const float2*)(wrow + 2 * q);
            memcpy(&Wreg[q], &w, 8);
        }
    }

    uint32_t h_local, m_local;
    asm volatile("{ .reg .u64 t; cvta.to.shared.u64 t, %1; cvt.u32.u64 %0, t; }"
                 : "=r"(h_local) : "l"((const float*)h_s));
    asm volatile("{ .reg .u64 t; cvta.to.shared.u64 t, %1; cvt.u32.u64 %0, t; }"
                 : "=r"(m_local) : "l"((const unsigned long long*)full_mbar));

    if (tid == 0) {
        asm volatile("mbarrier.init.shared.b64 [%0], %1;" :: "r"(m_local),     "r"(1u) : "memory");
        asm volatile("mbarrier.init.shared.b64 [%0], %1;" :: "r"(m_local + 8), "r"(1u) : "memory");
    }
    if (tid < 128) hstage[tid] = 0.f;
    __syncthreads();
    if (tid == 0) {
        asm volatile("mbarrier.arrive.expect_tx.shared.b64 _, [%0], %1;"
                     :: "r"(m_local),     "r"(4096u) : "memory");
        asm volatile("mbarrier.arrive.expect_tx.shared.b64 _, [%0], %1;"
                     :: "r"(m_local + 8), "r"(4096u) : "memory");
    }
    __syncthreads();
    asm volatile("barrier.cluster.arrive.aligned;\n\tbarrier.cluster.wait.aligned;" ::: "memory");

    uint32_t peer_h, peer_m;
    {
        uint32_t rk = (uint32_t)(tid >> 5);
        asm volatile("mapa.shared::cluster.u32 %0, %1, %2;" : "=r"(peer_h) : "r"(h_local), "r"(rk));
        asm volatile("mapa.shared::cluster.u32 %0, %1, %2;" : "=r"(peer_m) : "r"(m_local), "r"(rk));
    }
    const int i5 = tid & 31;
    const uint32_t push_off = ((uint32_t)(i5 >> 3) << 10) + ((uint32_t)brank << 7) + ((uint32_t)(i5 & 7) << 4);

    {
        const float4 v = *(const float4*)&hstage[i5 << 2];   // zeros
        asm volatile("st.async.shared::cluster.mbarrier::complete_tx::bytes.v4.f32 "
                     "[%0], {%1, %2, %3, %4}, [%5];"
                     :: "r"(peer_h + push_off), "f"(v.x), "f"(v.y), "f"(v.z), "f"(v.w),
                        "r"(peer_m) : "memory");
    }

    const float* xgb = g_xg + (((size_t)dir * BATCH + bg * 4) * TT) * NGATE;

    float c_state = 0.f;
    int t = dir ? (TT - 1) : 0;
    const int tstep = dir ? -1 : 1;

    float x0 = 0.f, x1 = 0.f, x2 = 0.f, x3 = 0.f;
    if (kh == 0) {
        x0 = xgb[((size_t)0 * TT + t) * NGATE + grow];
        x1 = xgb[((size_t)1 * TT + t) * NGATE + grow];
        x2 = xgb[((size_t)2 * TT + t) * NGATE + grow];
        x3 = xgb[((size_t)3 * TT + t) * NGATE + grow];
    }

    int ph0 = 0, ph1 = 0;
    for (int it = 0; it < TT; ++it) {
        const int b = it & 1;
        // ---- leader-warp wait: warp 0 polls, __syncthreads releases the rest ----
        if (tid < 32) {
            const uint32_t mb = m_local + ((uint32_t)b << 3);
            const uint32_t par = (uint32_t)(b ? ph1 : ph0);
            uint32_t done;
            asm volatile(
                "{\n\t.reg .pred p;\n\t"
                "mbarrier.try_wait.parity.acquire.cluster.shared::cta.b64 p, [%1], %2, 0x989680;\n\t"
                "selp.b32 %0, 1, 0, p;\n\t}"
                : "=r"(done) : "r"(mb), "r"(par) : "memory");
            while (!done) {
                asm volatile(
                    "{\n\t.reg .pred p;\n\t"
                    "mbarrier.try_wait.parity.acquire.cluster.shared::cta.b64 p, [%1], %2, 0x989680;\n\t"
                    "selp.b32 %0, 1, 0, p;\n\t}"
                    : "=r"(done) : "r"(mb), "r"(par) : "memory");
            }
            if (tid == 0 && it < TT - 1) {
                asm volatile("mbarrier.arrive.expect_tx.shared.b64 _, [%0], %1;"
                             :: "r"(mb), "r"(4096u) : "memory");
            }
        }
        if (b) ph1 ^= 1; else ph0 ^= 1;
        __syncthreads();

        unsigned long long acc0, acc1, acc2, acc3;
        if (kh == 0) {
            acc0 = pack2(x0, 0.f); acc1 = pack2(x1, 0.f);
            acc2 = pack2(x2, 0.f); acc3 = pack2(x3, 0.f);
        } else {
            acc0 = acc1 = acc2 = acc3 = 0ull;
        }

        const ulonglong2* hptr = reinterpret_cast<const ulonglong2*>(h_s + (b << 10) + (kh << 7));
        #pragma unroll
        for (int q = 0; q < 32; ++q) {
            ulonglong2 ha = hptr[q];
            ulonglong2 hb = hptr[q + 64];
            ulonglong2 hc = hptr[q + 128];
            ulonglong2 hd = hptr[q + 192];
            unsigned long long w0 = Wreg[2 * q], w1 = Wreg[2 * q + 1];
            ffma2(acc0, w0, ha.x); ffma2(acc1, w0, hb.x);
            ffma2(acc2, w0, hc.x); ffma2(acc3, w0, hd.x);
            ffma2(acc0, w1, ha.y); ffma2(acc1, w1, hb.y);
            ffma2(acc2, w1, hc.y); ffma2(acc3, w1, hd.y);
        }

        float s0 = fold2(acc0), s1 = fold2(acc1), s2 = fold2(acc2), s3 = fold2(acc3);
        if (kh == 0) {
            g_s[      j] = s0; g_s[128 + j] = s1; g_s[256 + j] = s2; g_s[384 + j] = s3;
        } else {
            rsum[      j] = s0; rsum[128 + j] = s1; rsum[256 + j] = s2; rsum[384 + j] = s3;
        }
        __syncthreads();

        float hval = 0.f;
        if (tid < 128) {
            const int bb   = tid >> 5;
            const int kloc = tid & 31;
            const int base = bb * 128 + kloc;
            float gi = g_s[base     ] + rsum[base     ];
            float gf = g_s[base + 32] + rsum[base + 32];
            float gg = g_s[base + 64] + rsum[base + 64];
            float go = g_s[base + 96] + rsum[base + 96];
            float i_ = sigmoid_fast(gi);
            float f_ = sigmoid_fast(gf);
            float g_ = tanh_fast(gg);
            float o_ = sigmoid_fast(go);
            c_state = f_ * c_state + i_ * g_;
            hval = o_ * tanh_fast(c_state);
            hstage[tid] = hval;
        }
        __syncthreads();

        {
            const float4 v = *(const float4*)&hstage[i5 << 2];
            const uint32_t dst = peer_h + ((uint32_t)(b ^ 1) << 12) + push_off;
            asm volatile("st.async.shared::cluster.mbarrier::complete_tx::bytes.v4.f32 "
                         "[%0], {%1, %2, %3, %4}, [%5];"
                         :: "r"(dst), "f"(v.x), "f"(v.y), "f"(v.z), "f"(v.w),
                            "r"(peer_m + ((uint32_t)(b ^ 1) << 3)) : "memory");
        }

        if (tid < 128) {
            const int bb   = tid >> 5;
            const int kloc = tid & 31;
            out[(((size_t)(bg * 4 + bb)) * TT + t) * OUTW + (dir << 8) + (brank << 5) + kloc] = hval;
        }
        if (kh == 0 && it + 1 < TT) {
            const int tnx = t + tstep;
            x0 = xgb[((size_t)0 * TT + tnx) * NGATE + grow];
            x1 = xgb[((size_t)1 * TT + tnx) * NGATE + grow];
            x2 = xgb[((size_t)2 * TT + tnx) * NGATE + grow];
            x3 = xgb[((size_t)3 * TT + tnx) * NGATE + grow];
        }

        t += tstep;
    }

    // drain final incoming pushes (they land in mbar[0])
    {
        const uint32_t mb = m_local;
        const uint32_t par = (uint32_t)ph0;
        uint32_t done;
        asm volatile(
            "{\n\t.reg .pred p;\n\t"
            "mbarrier.try_wait.parity.acquire.cluster.shared::cta.b64 p, [%1], %2, 0x989680;\n\t"
            "selp.b32 %0, 1, 0, p;\n\t}"
            : "=r"(done) : "r"(mb), "r"(par) : "memory");
        while (!done) {
            asm volatile(
                "{\n\t.reg .pred p;\n\t"
                "mbarrier.try_wait.parity.acquire.cluster.shared::cta.b64 p, [%1], %2, 0x989680;\n\t"
                "selp.b32 %0, 1, 0, p;\n\t}"
                : "=r"(done) : "r"(mb), "r"(par) : "memory");
        }
    }
    asm volatile("barrier.cluster.arrive.aligned;\n\tbarrier.cluster.wait.aligned;" ::: "memory");
}

// ---------------------------------------------------------------------------
extern "C" void kernel_launch(void* const* d_in, const int* in_sizes, int n_in,
                              void* d_out, int out_size)
{
    const float* x         = (const float*)d_in[0];
    const float* w_ih_l0f  = (const float*)d_in[1];
    const float* w_hh_l0f  = (const float*)d_in[2];
    const float* b_l0f     = (const float*)d_in[3];
    const float* w_ih_l0b  = (const float*)d_in[4];
    const float* w_hh_l0b  = (const float*)d_in[5];
    const float* b_l0b     = (const float*)d_in[6];
    const float* w_ih_l1f  = (const float*)d_in[7];
    const float* w_hh_l1f  = (const float*)d_in[8];
    const float* b_l1f     = (const float*)d_in[9];
    const float* w_ih_l1b  = (const float*)d_in[10];
    const float* w_hh_l1b  = (const float*)d_in[11];
    const float* b_l1b     = (const float*)d_in[12];
    float* out = (float*)d_out;

    float* h1 = nullptr;
    cudaGetSymbolAddress((void**)&h1, g_h1);

    const int smemB = SB_TOTAL * 4;   // 30720 B
    cudaFuncSetAttribute(gemm_bf, cudaFuncAttributeMaxDynamicSharedMemorySize, smemB);

    dim3 tgrid(16, 128, 2);   // N/64, M/128, dirs

    // Layer 0 (K=256, 16 stages of 16)
    gemm_bf<<<tgrid, 256, smemB>>>(x, 256, 16, w_ih_l0f, b_l0f, w_ih_l0b, b_l0b);
    lstm_rec<<<128, 256>>>(w_hh_l0f, w_hh_l0b, h1);

    // Layer 1 (K=512, 32 stages of 16)
    gemm_bf<<<tgrid, 256, smemB>>>(h1, 512, 32, w_ih_l1f, b_l1f, w_ih_l1b, b_l1b);
    lstm_rec<<<128, 256>>>(w_hh_l1f, w_hh_l1b, out);
}

// round 17
// speedup vs baseline: 1.1350x; 1.0004x over previous
#include <cuda_runtime.h>
#include <cuda_bf16.h>
#include <cstdint>
#include <cstring>

#define BATCH 32
#define TT    512
#define NGATE 1024   // 4*H
#define HDIM  256
#define OUTW  512

// Scratch (static device globals — no allocation allowed)
__device__ float g_xg[(size_t)2 * BATCH * TT * NGATE];   // pre-activations (both dirs)
__device__ float g_h1[(size_t)BATCH * TT * OUTW];        // layer-0 output (fwd||bwd concat)

// ---------------- f32x2 helpers (recurrence) ----------------
__device__ __forceinline__ void ffma2(unsigned long long& d, unsigned long long a, unsigned long long b) {
    asm("fma.rn.f32x2 %0, %1, %2, %0;" : "+l"(d) : "l"(a), "l"(b));
}
__device__ __forceinline__ float fold2(unsigned long long v) {
    float2 f; memcpy(&f, &v, 8); return f.x + f.y;
}
__device__ __forceinline__ unsigned long long pack2(float lo, float hi) {
    unsigned long long u;
    asm("mov.b64 %0, {%1, %2};" : "=l"(u) : "f"(lo), "f"(hi));
    return u;
}

// ===========================================================================
// bf16 2-split mma.sync GEMM (unchanged from R16 — best passing, ~0.72ms)
// ===========================================================================
__device__ __forceinline__ uint32_t pack_bf16x2(float lo_elem, float hi_elem) {
    __nv_bfloat162 v;
    v.x = __float2bfloat16(lo_elem);
    v.y = __float2bfloat16(hi_elem);
    uint32_t u; memcpy(&u, &v, 4);
    return u;
}
__device__ __forceinline__ float bf_hi_part(float x) {
    return __bfloat162float(__float2bfloat16(x));
}
__device__ __forceinline__ void mma_bf16(float c[4],
    uint32_t a0, uint32_t a1, uint32_t a2, uint32_t a3,
    uint32_t b0, uint32_t b1)
{
    asm("mma.sync.aligned.m16n8k16.row.col.f32.bf16.bf16.f32 "
        "{%0,%1,%2,%3}, {%4,%5,%6,%7}, {%8,%9}, {%0,%1,%2,%3};"
        : "+f"(c[0]), "+f"(c[1]), "+f"(c[2]), "+f"(c[3])
        : "r"(a0), "r"(a1), "r"(a2), "r"(a3), "r"(b0), "r"(b1));
}

#define SB_AH 0       // 2 bufs x 1280 words (128 rows x 10)
#define SB_AL 2560
#define SB_BH 5120    // 2 bufs x 640 words (64 rows x 10)
#define SB_BL 6400
#define SB_TOTAL 7680 // words -> 30720 bytes dynamic smem

__global__ __launch_bounds__(256, 2) void gemm_bf(
    const float* __restrict__ src, int K, int nst,
    const float* __restrict__ Wf, const float* __restrict__ bf,
    const float* __restrict__ Wb, const float* __restrict__ bb)
{
    extern __shared__ __align__(16) uint32_t sm[];
    const int dir = blockIdx.z;
    const float* __restrict__ W    = dir ? Wb : Wf;
    const float* __restrict__ bias = dir ? bb : bf;
    const int j0 = blockIdx.x * 64;
    const int r0 = blockIdx.y * 128;

    const int tid  = threadIdx.x;
    const int wid  = tid >> 5;
    const int lane = tid & 31;
    const int g    = lane >> 2;
    const int tg   = lane & 3;
    const int mrow = (wid & 3) * 32;
    const int ncol = (wid >> 2) * 32;

    const int arow  = tid >> 1;
    const int ahalf = tid & 1;
    const int brow  = tid >> 2;
    const int bq4   = (tid & 3) * 4;
    const float* aptr = src + (size_t)(r0 + arow) * K + ahalf * 8;
    const float* bptr = W   + (size_t)(j0 + brow) * K + bq4;

    float c[2][4][4];
    #pragma unroll
    for (int i = 0; i < 2; i++)
        #pragma unroll
        for (int jn = 0; jn < 4; jn++)
            #pragma unroll
            for (int u = 0; u < 4; u++) c[i][jn][u] = 0.f;

    float apf[8]; float bpf[4];
    auto ldg_stage = [&](int s) {
        float4 v0 = *(const float4*)(aptr + s * 16);
        float4 v1 = *(const float4*)(aptr + s * 16 + 4);
        apf[0]=v0.x; apf[1]=v0.y; apf[2]=v0.z; apf[3]=v0.w;
        apf[4]=v1.x; apf[5]=v1.y; apf[6]=v1.z; apf[7]=v1.w;
        float4 w0 = *(const float4*)(bptr + s * 16);
        bpf[0]=w0.x; bpf[1]=w0.y; bpf[2]=w0.z; bpf[3]=w0.w;
    };
    auto sts_stage = [&](int buf) {
        uint32_t* ah = sm + SB_AH + buf * 1280 + arow * 10;
        uint32_t* al = sm + SB_AL + buf * 1280 + arow * 10;
        #pragma unroll
        for (int qq = 0; qq < 4; qq++) {
            const int kp  = ahalf * 4 + qq;
            const int pos = (kp & 3) * 2 + (kp >> 2);
            float x0 = apf[2 * qq], x1 = apf[2 * qq + 1];
            float h0 = bf_hi_part(x0), h1 = bf_hi_part(x1);
            ah[pos] = pack_bf16x2(x0, x1);
            al[pos] = pack_bf16x2(x0 - h0, x1 - h1);
        }
        uint32_t* bh = sm + SB_BH + buf * 640 + brow * 10;
        uint32_t* bl = sm + SB_BL + buf * 640 + brow * 10;
        #pragma unroll
        for (int qq2 = 0; qq2 < 2; qq2++) {
            const int kp  = (tid & 3) * 2 + qq2;
            const int pos = (kp & 3) * 2 + (kp >> 2);
            float x0 = bpf[2 * qq2], x1 = bpf[2 * qq2 + 1];
            float h0 = bf_hi_part(x0), h1 = bf_hi_part(x1);
            bh[pos] = pack_bf16x2(x0, x1);
            bl[pos] = pack_bf16x2(x0 - h0, x1 - h1);
        }
    };
    auto compute_stage = [&](int buf) {
        const uint32_t* ah = sm + SB_AH + buf * 1280;
        const uint32_t* al = sm + SB_AL + buf * 1280;
        const uint32_t* bh = sm + SB_BH + buf * 640;
        const uint32_t* bl = sm + SB_BL + buf * 640;
        uint32_t fah[2][4], fal[2][4], fbh[4][2], fbl[4][2];
        #pragma unroll
        for (int i = 0; i < 2; i++) {
            const int base = (mrow + i * 16 + g) * 10 + tg * 2;
            uint2 h0 = *(const uint2*)(ah + base);
            uint2 h1 = *(const uint2*)(ah + base + 80);
            uint2 l0 = *(const uint2*)(al + base);
            uint2 l1 = *(const uint2*)(al + base + 80);
            fah[i][0] = h0.x; fah[i][2] = h0.y;
            fah[i][1] = h1.x; fah[i][3] = h1.y;
            fal[i][0] = l0.x; fal[i][2] = l0.y;
            fal[i][1] = l1.x; fal[i][3] = l1.y;
        }
        #pragma unroll
        for (int jn = 0; jn < 4; jn++) {
            const int wb = (ncol + jn * 8 + g) * 10 + tg * 2;
            uint2 hb = *(const uint2*)(bh + wb);
            uint2 lb = *(const uint2*)(bl + wb);
            fbh[jn][0] = hb.x; fbh[jn][1] = hb.y;
            fbl[jn][0] = lb.x; fbl[jn][1] = lb.y;
        }
        #pragma unroll
        for (int i = 0; i < 2; i++)
            #pragma unroll
            for (int jn = 0; jn < 4; jn++) {
                mma_bf16(c[i][jn], fah[i][0], fah[i][1], fah[i][2], fah[i][3], fbh[jn][0], fbh[jn][1]);
                mma_bf16(c[i][jn], fah[i][0], fah[i][1], fah[i][2], fah[i][3], fbl[jn][0], fbl[jn][1]);
                mma_bf16(c[i][jn], fal[i][0], fal[i][1], fal[i][2], fal[i][3], fbh[jn][0], fbh[jn][1]);
            }
    };

    ldg_stage(0);
    sts_stage(0);
    __syncthreads();
    for (int s = 0; s < nst; ++s) {
        if (s + 1 < nst) ldg_stage(s + 1);
        compute_stage(s & 1);
        if (s + 1 < nst) sts_stage((s + 1) & 1);
        __syncthreads();
    }

    float* outp = g_xg + ((size_t)dir * (BATCH * TT)) * NGATE;
    #pragma unroll
    for (int i = 0; i < 2; i++) {
        #pragma unroll
        for (int jn = 0; jn < 4; jn++) {
            const int col = j0 + ncol + jn * 8 + 2 * tg;
            const float b0v = __ldg(&bias[col]);
            const float b1v = __ldg(&bias[col + 1]);
            const int row = r0 + mrow + i * 16 + g;
            float2 v0 = make_float2(c[i][jn][0] + b0v, c[i][jn][1] + b1v);
            float2 v1 = make_float2(c[i][jn][2] + b0v, c[i][jn][3] + b1v);
            *(float2*)&outp[(size_t)row * NGATE + col] = v0;
            *(float2*)&outp[(size_t)(row + 8) * NGATE + col] = v1;
        }
    }
}

// ---------------------------------------------------------------------------
// Recurrence (R16 base, ONE change: waits use acquire.CTA, not acquire.cluster.
// st.async's complete_tx guarantees data-before-completion in our smem; cta
// acquire orders our own smem reads. cluster-scope acquire lowers to an L1D
// invalidate (CCTL.IVALL) per the B300 notes — suspected per-step fixed cost.)
// ---------------------------------------------------------------------------
__device__ __forceinline__ float sigmoid_fast(float x) {
    return __fdividef(1.f, 1.f + __expf(-x));
}
__device__ __forceinline__ float tanh_fast(float x) {
    float xc = fminf(fmaxf(x, -15.f), 15.f);
    float e = __expf(2.f * xc);
    return __fdividef(e - 1.f, e + 1.f);
}

__device__ __forceinline__ void mbar_wait_cta(uint32_t mb, uint32_t par) {
    uint32_t done;
    asm volatile(
        "{\n\t.reg .pred p;\n\t"
        "mbarrier.try_wait.parity.acquire.cta.shared::cta.b64 p, [%1], %2, 0x989680;\n\t"
        "selp.b32 %0, 1, 0, p;\n\t}"
        : "=r"(done) : "r"(mb), "r"(par) : "memory");
    while (!done) {
        asm volatile(
            "{\n\t.reg .pred p;\n\t"
            "mbarrier.try_wait.parity.acquire.cta.shared::cta.b64 p, [%1], %2, 0x989680;\n\t"
            "selp.b32 %0, 1, 0, p;\n\t}"
            : "=r"(done) : "r"(mb), "r"(par) : "memory");
    }
}

__global__ __launch_bounds__(256, 1) __cluster_dims__(8, 1, 1)
void lstm_rec(const float* __restrict__ whhF, const float* __restrict__ whhB,
              float* __restrict__ out)
{
    __shared__ __align__(16) float h_s[2 * 1024];   // [2 buf][4 batch][256]
    __shared__ float g_s [512];
    __shared__ float rsum[512];
    __shared__ __align__(16) float hstage[128];
    __shared__ __align__(8) unsigned long long full_mbar[2];

    const int tid   = threadIdx.x;
    const int j     = tid & 127;
    const int kh    = tid >> 7;
    const int brank = blockIdx.x & 7;
    const int cid   = blockIdx.x >> 3;
    const int dir   = cid >> 3;
    const int bg    = cid & 7;
    const float* __restrict__ whh = dir ? whhB : whhF;

    const int gate = j >> 5;
    const int kl   = j & 31;
    const int grow = (gate << 8) + (brank << 5) + kl;

    unsigned long long Wreg[64];
    {
        const float* wrow = whh + (size_t)grow * HDIM + (kh << 7);
        #pragma unroll
        for (int q = 0; q < 64; ++q) {
            float2 w = *(const float2*)(wrow + 2 * q);
            memcpy(&Wreg[q], &w, 8);
        }
    }

    uint32_t h_local, m_local;
    asm volatile("{ .reg .u64 t; cvta.to.shared.u64 t, %1; cvt.u32.u64 %0, t; }"
                 : "=r"(h_local) : "l"((const float*)h_s));
    asm volatile("{ .reg .u64 t; cvta.to.shared.u64 t, %1; cvt.u32.u64 %0, t; }"
                 : "=r"(m_local) : "l"((const unsigned long long*)full_mbar));

    if (tid == 0) {
        asm volatile("mbarrier.init.shared.b64 [%0], %1;" :: "r"(m_local),     "r"(1u) : "memory");
        asm volatile("mbarrier.init.shared.b64 [%0], %1;" :: "r"(m_local + 8), "r"(1u) : "memory");
    }
    if (tid < 128) hstage[tid] = 0.f;
    __syncthreads();
    if (tid == 0) {
        asm volatile("mbarrier.arrive.expect_tx.shared.b64 _, [%0], %1;"
                     :: "r"(m_local),     "r"(4096u) : "memory");
        asm volatile("mbarrier.arrive.expect_tx.shared.b64 _, [%0], %1;"
                     :: "r"(m_local + 8), "r"(4096u) : "memory");
    }
    __syncthreads();
    asm volatile("barrier.cluster.arrive.aligned;\n\tbarrier.cluster.wait.aligned;" ::: "memory");

    uint32_t peer_h, peer_m;
    {
        uint32_t rk = (uint32_t)(tid >> 5);
        asm volatile("mapa.shared::cluster.u32 %0, %1, %2;" : "=r"(peer_h) : "r"(h_local), "r"(rk));
        asm volatile("mapa.shared::cluster.u32 %0, %1, %2;" : "=r"(peer_m) : "r"(m_local), "r"(rk));
    }
    const int i5 = tid & 31;
    const uint32_t push_off = ((uint32_t)(i5 >> 3) << 10) + ((uint32_t)brank << 7) + ((uint32_t)(i5 & 7) << 4);

    {
        const float4 v = *(const float4*)&hstage[i5 << 2];   // zeros
        asm volatile("st.async.shared::cluster.mbarrier::complete_tx::bytes.v4.f32 "
                     "[%0], {%1, %2, %3, %4}, [%5];"
                     :: "r"(peer_h + push_off), "f"(v.x), "f"(v.y), "f"(v.z), "f"(v.w),
                        "r"(peer_m) : "memory");
    }

    const float* xgb = g_xg + (((size_t)dir * BATCH + bg * 4) * TT) * NGATE;

    float c_state = 0.f;
    int t = dir ? (TT - 1) : 0;
    const int tstep = dir ? -1 : 1;

    float x0 = 0.f, x1 = 0.f, x2 = 0.f, x3 = 0.f;
    if (kh == 0) {
        x0 = xgb[((size_t)0 * TT + t) * NGATE + grow];
        x1 = xgb[((size_t)1 * TT + t) * NGATE + grow];
        x2 = xgb[((size_t)2 * TT + t) * NGATE + grow];
        x3 = xgb[((size_t)3 * TT + t) * NGATE + grow];
    }

    int ph0 = 0, ph1 = 0;
    for (int it = 0; it < TT; ++it) {
        const int b = it & 1;
        // ---- leader-warp wait (acquire.CTA): warp 0 polls, syncthreads releases ----
        if (tid < 32) {
            const uint32_t mb = m_local + ((uint32_t)b << 3);
            mbar_wait_cta(mb, (uint32_t)(b ? ph1 : ph0));
            if (tid == 0 && it < TT - 1) {
                asm volatile("mbarrier.arrive.expect_tx.shared.b64 _, [%0], %1;"
                             :: "r"(mb), "r"(4096u) : "memory");
            }
        }
        if (b) ph1 ^= 1; else ph0 ^= 1;
        __syncthreads();

        unsigned long long acc0, acc1, acc2, acc3;
        if (kh == 0) {
            acc0 = pack2(x0, 0.f); acc1 = pack2(x1, 0.f);
            acc2 = pack2(x2, 0.f); acc3 = pack2(x3, 0.f);
        } else {
            acc0 = acc1 = acc2 = acc3 = 0ull;
        }

        const ulonglong2* hptr = reinterpret_cast<const ulonglong2*>(h_s + (b << 10) + (kh << 7));
        #pragma unroll
        for (int q = 0; q < 32; ++q) {
            ulonglong2 ha = hptr[q];
            ulonglong2 hb = hptr[q + 64];
            ulonglong2 hc = hptr[q + 128];
            ulonglong2 hd = hptr[q + 192];
            unsigned long long w0 = Wreg[2 * q], w1 = Wreg[2 * q + 1];
            ffma2(acc0, w0, ha.x); ffma2(acc1, w0, hb.x);
            ffma2(acc2, w0, hc.x); ffma2(acc3, w0, hd.x);
            ffma2(acc0, w1, ha.y); ffma2(acc1, w1, hb.y);
            ffma2(acc2, w1, hc.y); ffma2(acc3, w1, hd.y);
        }

        float s0 = fold2(acc0), s1 = fold2(acc1), s2 = fold2(acc2), s3 = fold2(acc3);
        if (kh == 0) {
            g_s[      j] = s0; g_s[128 + j] = s1; g_s[256 + j] = s2; g_s[384 + j] = s3;
        } else {
            rsum[      j] = s0; rsum[128 + j] = s1; rsum[256 + j] = s2; rsum[384 + j] = s3;
        }
        __syncthreads();

        float hval = 0.f;
        if (tid < 128) {
            const int bb   = tid >> 5;
            const int kloc = tid & 31;
            const int base = bb * 128 + kloc;
            float gi = g_s[base     ] + rsum[base     ];
            float gf = g_s[base + 32] + rsum[base + 32];
            float gg = g_s[base + 64] + rsum[base + 64];
            float go = g_s[base + 96] + rsum[base + 96];
            float i_ = sigmoid_fast(gi);
            float f_ = sigmoid_fast(gf);
            float g_ = tanh_fast(gg);
            float o_ = sigmoid_fast(go);
            c_state = f_ * c_state + i_ * g_;
            hval = o_ * tanh_fast(c_state);
            hstage[tid] = hval;
        }
        __syncthreads();

        {
            const float4 v = *(const float4*)&hstage[i5 << 2];
            const uint32_t dst = peer_h + ((uint32_t)(b ^ 1) << 12) + push_off;
            asm volatile("st.async.shared::cluster.mbarrier::complete_tx::bytes.v4.f32 "
                         "[%0], {%1, %2, %3, %4}, [%5];"
                         :: "r"(dst), "f"(v.x), "f"(v.y), "f"(v.z), "f"(v.w),
                            "r"(peer_m + ((uint32_t)(b ^ 1) << 3)) : "memory");
        }

        if (tid < 128) {
            const int bb   = tid >> 5;
            const int kloc = tid & 31;
            out[(((size_t)(bg * 4 + bb)) * TT + t) * OUTW + (dir << 8) + (brank << 5) + kloc] = hval;
        }
        if (kh == 0 && it + 1 < TT) {
            const int tnx = t + tstep;
            x0 = xgb[((size_t)0 * TT + tnx) * NGATE + grow];
            x1 = xgb[((size_t)1 * TT + tnx) * NGATE + grow];
            x2 = xgb[((size_t)2 * TT + tnx) * NGATE + grow];
            x3 = xgb[((size_t)3 * TT + tnx) * NGATE + grow];
        }

        t += tstep;
    }

    // drain final incoming pushes (they land in mbar[0])
    mbar_wait_cta(m_local, (uint32_t)ph0);
    asm volatile("barrier.cluster.arrive.aligned;\n\tbarrier.cluster.wait.aligned;" ::: "memory");
}

// ---------------------------------------------------------------------------
extern "C" void kernel_launch(void* const* d_in, const int* in_sizes, int n_in,
                              void* d_out, int out_size)
{
    const float* x         = (const float*)d_in[0];
    const float* w_ih_l0f  = (const float*)d_in[1];
    const float* w_hh_l0f  = (const float*)d_in[2];
    const float* b_l0f     = (const float*)d_in[3];
    const float* w_ih_l0b  = (const float*)d_in[4];
    const float* w_hh_l0b  = (const float*)d_in[5];
    const float* b_l0b     = (const float*)d_in[6];
    const float* w_ih_l1f  = (const float*)d_in[7];
    const float* w_hh_l1f  = (const float*)d_in[8];
    const float* b_l1f     = (const float*)d_in[9];
    const float* w_ih_l1b  = (const float*)d_in[10];
    const float* w_hh_l1b  = (const float*)d_in[11];
    const float* b_l1b     = (const float*)d_in[12];
    float* out = (float*)d_out;

    float* h1 = nullptr;
    cudaGetSymbolAddress((void**)&h1, g_h1);

    const int smemB = SB_TOTAL * 4;   // 30720 B
    cudaFuncSetAttribute(gemm_bf, cudaFuncAttributeMaxDynamicSharedMemorySize, smemB);

    dim3 tgrid(16, 128, 2);   // N/64, M/128, dirs

    // Layer 0 (K=256, 16 stages of 16)
    gemm_bf<<<tgrid, 256, smemB>>>(x, 256, 16, w_ih_l0f, b_l0f, w_ih_l0b, b_l0b);
    lstm_rec<<<128, 256>>>(w_hh_l0f, w_hh_l0b, h1);

    // Layer 1 (K=512, 32 stages of 16)
    gemm_bf<<<tgrid, 256, smemB>>>(h1, 512, 32, w_ih_l1f, b_l1f, w_ih_l1b, b_l1b);
    lstm_rec<<<128, 256>>>(w_hh_l1f, w_hh_l1b, out);
}